// round 4
// baseline (speedup 1.0000x reference)
#include <cuda_runtime.h>
#include <cstdint>

#define N_NODES 100000
#define IN_DIM  512
#define HIDDEN  16
#define OUT_DIM 64

__device__ float g_deg [N_NODES];
__device__ float g_dinv[N_NODES];
__device__ float g_hs1 [N_NODES * HIDDEN];
__device__ float g_acc1[N_NODES * HIDDEN];
__device__ float g_zs  [N_NODES * HIDDEN];
__device__ float g_acc2[N_NODES * HIDDEN];

// ---------------------------------------------------------------------------
__global__ void k_zero() {
    int stride = gridDim.x * blockDim.x;
    int i = blockIdx.x * blockDim.x + threadIdx.x;
    for (int j = i; j < N_NODES * HIDDEN; j += stride) {
        g_acc1[j] = 0.f;
        g_acc2[j] = 0.f;
    }
    for (int j = i; j < N_NODES; j += stride) g_deg[j] = 0.f;
}

__global__ void k_degree(const int* __restrict__ dst, int E) {
    int i = blockIdx.x * blockDim.x + threadIdx.x;
    int e0 = i << 2;
    if (e0 + 3 < E) {
        int4 d = *reinterpret_cast<const int4*>(dst + e0);
        atomicAdd(&g_deg[d.x], 1.0f);
        atomicAdd(&g_deg[d.y], 1.0f);
        atomicAdd(&g_deg[d.z], 1.0f);
        atomicAdd(&g_deg[d.w], 1.0f);
    } else {
        for (int e = e0; e < E; e++) atomicAdd(&g_deg[dst[e]], 1.0f);
    }
}

__global__ void k_dinv() {
    int i = blockIdx.x * blockDim.x + threadIdx.x;
    if (i < N_NODES) g_dinv[i] = rsqrtf(g_deg[i] + 1.0f);   // +1 = self-loop
}

// ---------------------------------------------------------------------------
// GEMM1: hs1[n][f] = (sum_k x[n][k] * W1[k][f]) * dinv[n]
// 256 threads, 256 rows/block; thread = 4 rows (stride 64) x 4 features.
// cp.async double-buffered staging of x, KC=16. W1 via __ldg (L1-resident).
#define G1_ROWS 256
#define G1_KC   16
#define XS_STR  20                       // floats per row (pad 4)
#define N_CHUNK (IN_DIM / G1_KC)         // 32

__device__ __forceinline__ void cp_async16(unsigned int saddr, const void* gptr) {
    asm volatile("cp.async.cg.shared.global [%0], [%1], 16;"
                 :: "r"(saddr), "l"(gptr) : "memory");
}

__global__ __launch_bounds__(256) void k_gemm1(const float* __restrict__ x,
                                               const float* __restrict__ W1) {
    __shared__ float xs[2][G1_ROWS * XS_STR];   // 2 x 20480 B

    int tid = threadIdx.x;
    int fg4 = tid & 3;                   // feature float4 index: 0..3
    int rg  = tid >> 2;                  // row group: 0..63
    int row0 = blockIdx.x * G1_ROWS;

    const float4* xg = reinterpret_cast<const float4*>(x);
    const float4* W4 = reinterpret_cast<const float4*>(W1);

    // Precompute staging addresses for this thread (4 x 16B per chunk)
    int s_rr[4], s_cc[4];
    const float4* s_g[4];
    #pragma unroll
    for (int l = 0; l < 4; l++) {
        int idx = tid + l * 256;         // 0..1023
        s_rr[l] = idx >> 2;              // 0..255
        s_cc[l] = idx & 3;               // float4 col within chunk
        int grow = row0 + s_rr[l];
        if (grow >= N_NODES) grow = N_NODES - 1;
        s_g[l] = &xg[(size_t)grow * (IN_DIM / 4) + s_cc[l]];
    }

    float acc[4][4];
    #pragma unroll
    for (int i = 0; i < 4; i++)
        #pragma unroll
        for (int j = 0; j < 4; j++) acc[i][j] = 0.f;

    // Stage chunk 0
    #pragma unroll
    for (int l = 0; l < 4; l++) {
        unsigned int sa = (unsigned int)__cvta_generic_to_shared(
            &xs[0][s_rr[l] * XS_STR + s_cc[l] * 4]);
        cp_async16(sa, s_g[l]);
    }
    asm volatile("cp.async.commit_group;");

    for (int c = 0; c < N_CHUNK; c++) {
        int cur = c & 1;
        if (c + 1 < N_CHUNK) {
            int kc4 = (c + 1) * (G1_KC / 4);
            #pragma unroll
            for (int l = 0; l < 4; l++) {
                unsigned int sa = (unsigned int)__cvta_generic_to_shared(
                    &xs[cur ^ 1][s_rr[l] * XS_STR + s_cc[l] * 4]);
                cp_async16(sa, s_g[l] + kc4);
            }
            asm volatile("cp.async.commit_group;");
            asm volatile("cp.async.wait_group 1;");
        } else {
            asm volatile("cp.async.wait_group 0;");
        }
        __syncthreads();

        int kc = c * G1_KC;
        #pragma unroll
        for (int kk = 0; kk < G1_KC; kk += 4) {
            float4 xv[4];
            #pragma unroll
            for (int i = 0; i < 4; i++)
                xv[i] = *reinterpret_cast<const float4*>(
                    &xs[cur][(rg + i * 64) * XS_STR + kk]);
            #pragma unroll
            for (int j = 0; j < 4; j++) {
                float4 w = __ldg(&W4[(kc + kk + j) * 4 + fg4]);
                #pragma unroll
                for (int i = 0; i < 4; i++) {
                    float xj = reinterpret_cast<const float*>(&xv[i])[j];
                    acc[i][0] = fmaf(xj, w.x, acc[i][0]);
                    acc[i][1] = fmaf(xj, w.y, acc[i][1]);
                    acc[i][2] = fmaf(xj, w.z, acc[i][2]);
                    acc[i][3] = fmaf(xj, w.w, acc[i][3]);
                }
            }
        }
        __syncthreads();
    }

    #pragma unroll
    for (int i = 0; i < 4; i++) {
        int r = row0 + rg + i * 64;
        if (r < N_NODES) {
            float dv = g_dinv[r];
            float4 o = make_float4(acc[i][0] * dv, acc[i][1] * dv,
                                   acc[i][2] * dv, acc[i][3] * dv);
            *reinterpret_cast<float4*>(&g_hs1[r * HIDDEN + (fg4 << 2)]) = o;
        }
    }
}

// ---------------------------------------------------------------------------
// Edge scatter: acc[dst] += table[src] (16 floats).
// Thread = one quarter (4 floats) of FOUR consecutive edges:
//   2 vector idx loads + 4 independent gathers + 4 REDs -> high MLP.
__device__ __forceinline__ void red_add_v4(float* p, float4 v) {
    asm volatile("red.global.add.v4.f32 [%0], {%1,%2,%3,%4};"
                 :: "l"(p), "f"(v.x), "f"(v.y), "f"(v.z), "f"(v.w) : "memory");
}

__global__ void k_scatter(const int* __restrict__ src, const int* __restrict__ dst,
                          int E, int phase) {
    int t = blockIdx.x * blockDim.x + threadIdx.x;
    int e0 = (t >> 2) << 2;
    if (e0 >= E) return;
    int q = (t & 3) << 2;
    const float* tab = phase ? g_zs   : g_hs1;
    float*       acc = phase ? g_acc2 : g_acc1;

    if (e0 + 3 < E) {
        int4 s4 = *reinterpret_cast<const int4*>(src + e0);
        int4 d4 = *reinterpret_cast<const int4*>(dst + e0);
        float4 v0 = *reinterpret_cast<const float4*>(tab + s4.x * HIDDEN + q);
        float4 v1 = *reinterpret_cast<const float4*>(tab + s4.y * HIDDEN + q);
        float4 v2 = *reinterpret_cast<const float4*>(tab + s4.z * HIDDEN + q);
        float4 v3 = *reinterpret_cast<const float4*>(tab + s4.w * HIDDEN + q);
        red_add_v4(acc + d4.x * HIDDEN + q, v0);
        red_add_v4(acc + d4.y * HIDDEN + q, v1);
        red_add_v4(acc + d4.z * HIDDEN + q, v2);
        red_add_v4(acc + d4.w * HIDDEN + q, v3);
    } else {
        for (int e = e0; e < E; e++) {
            int s = src[e], d = dst[e];
            float4 v = *reinterpret_cast<const float4*>(tab + s * HIDDEN + q);
            red_add_v4(acc + d * HIDDEN + q, v);
        }
    }
}

// ---------------------------------------------------------------------------
// Layer-1 epilogue: zs = relu(dinv*(acc1 + hs1) + b1) * dinv   (float4)
__global__ void k_mid(const float* __restrict__ b1) {
    int i = blockIdx.x * blockDim.x + threadIdx.x;          // float4 index
    if (i >= N_NODES * HIDDEN / 4) return;
    int node = i >> 2;
    int f4 = (i & 3) << 2;
    float dv = g_dinv[node];
    float4 a = *reinterpret_cast<const float4*>(&g_acc1[i * 4]);
    float4 h = *reinterpret_cast<const float4*>(&g_hs1[i * 4]);
    float4 b = *reinterpret_cast<const float4*>(&b1[f4]);
    float4 z;
    z.x = fmaxf(fmaf(dv, a.x + h.x, b.x), 0.f) * dv;
    z.y = fmaxf(fmaf(dv, a.y + h.y, b.y), 0.f) * dv;
    z.z = fmaxf(fmaf(dv, a.z + h.z, b.z), 0.f) * dv;
    z.w = fmaxf(fmaf(dv, a.w + h.w, b.w), 0.f) * dv;
    *reinterpret_cast<float4*>(&g_zs[i * 4]) = z;
}

// ---------------------------------------------------------------------------
// Final: agg[d] = dinv[d]*(acc2[d] + zs[d]);  out[d] = agg @ W2 + b2
__global__ __launch_bounds__(256) void k_final(const float* __restrict__ W2,
                                               const float* __restrict__ b2,
                                               float* __restrict__ out) {
    __shared__ float W2s[HIDDEN * OUT_DIM];
    __shared__ float aggs[4][HIDDEN];
    int tid = threadIdx.x;
    for (int j = tid; j < HIDDEN * OUT_DIM; j += 256) W2s[j] = W2[j];

    int n = tid >> 6;
    int o = tid & 63;
    int node = blockIdx.x * 4 + n;

    if (o < HIDDEN) {
        float dv = g_dinv[node];
        int idx = node * HIDDEN + o;
        aggs[n][o] = dv * (g_acc2[idx] + g_zs[idx]);
    }
    __syncthreads();

    float acc = b2[o];
    #pragma unroll
    for (int k = 0; k < HIDDEN; k++)
        acc = fmaf(aggs[n][k], W2s[k * OUT_DIM + o], acc);
    out[(size_t)node * OUT_DIM + o] = acc;
}

// ---------------------------------------------------------------------------
extern "C" void kernel_launch(void* const* d_in, const int* in_sizes, int n_in,
                              void* d_out, int out_size) {
    const float* x  = (const float*)d_in[0];
    const float* W1 = (const float*)d_in[1];
    const float* b1 = (const float*)d_in[2];
    const float* W2 = (const float*)d_in[3];
    const float* b2 = (const float*)d_in[4];
    const int*   ei = (const int*)d_in[5];
    float* out = (float*)d_out;

    int E = in_sizes[5] / 2;
    const int* src = ei;
    const int* dst = ei + E;

    k_zero  <<<1024, 256>>>();
    k_degree<<<(E / 4 + 255) / 256, 256>>>(dst, E);
    k_dinv  <<<(N_NODES + 255) / 256, 256>>>();
    k_gemm1 <<<(N_NODES + G1_ROWS - 1) / G1_ROWS, 256>>>(x, W1);
    k_scatter<<<(E + 255) / 256, 256>>>(src, dst, E, 0);
    k_mid   <<<(N_NODES * HIDDEN / 4 + 255) / 256, 256>>>(b1);
    k_scatter<<<(E + 255) / 256, 256>>>(src, dst, E, 1);
    k_final <<<N_NODES / 4, 256>>>(W2, b2, out);
}